// round 5
// baseline (speedup 1.0000x reference)
#include <cuda_runtime.h>
#include <cstddef>
#include <cstdint>

// FISM scoring: B=16384 rows, K=50 neighbors (contiguous slice of I_U),
// NNEG=20, D=128. Two-kernel split for occupancy:
//   k1: gather-sum -> p_ctx_avg (8MB __device__ scratch)
//   k2: 21 dot products + biases -> out
// L2 evict_last (via createpolicy + L2::cache_hint -- the form this ptxas
// accepts for 128-bit loads) keeps the 102MB P+Q tables L2-resident.

#define FB    16384
#define FK    50
#define FNNEG 20
#define FD    128
#define WPB   8                      // warps (rows) per 256-thread block

__device__ __align__(16) float g_pctx[(size_t)FB * FD];   // 8 MB scratch

// float4 gather with L2 evict_last cache hint
__device__ __forceinline__ float4 ldg_el4(const float4* p) {
    float4 v;
    asm("{\n\t"
        ".reg .b64 pol;\n\t"
        "createpolicy.fractional.L2::evict_last.b64 pol, 1.0;\n\t"
        "ld.global.nc.L2::cache_hint.v4.f32 {%0,%1,%2,%3}, [%4], pol;\n\t"
        "}"
        : "=f"(v.x), "=f"(v.y), "=f"(v.z), "=f"(v.w) : "l"(p));
    return v;
}

// ---------------- kernel 1: neighbor gather + sum ------------------------
template<bool VEC>
__global__ __launch_bounds__(256, 6) void fism_gather(
    const int*   __restrict__ I,
    const int*   __restrict__ I_U,
    const int*   __restrict__ N_U,
    const int*   __restrict__ I_in,
    const float* __restrict__ P)
{
    const int wid  = threadIdx.x >> 5;
    const int lane = threadIdx.x & 31;
    const int b    = blockIdx.x * WPB + wid;        // FB = 2048*8 exact

    __shared__ int s_idx[WPB][FK];
    {
        const int* src = I_U + (size_t)b * FK;
        s_idx[wid][lane] = src[lane];
        if (lane < FK - 32) s_idx[wid][32 + lane] = src[32 + lane];
    }
    __syncwarp();

    const int   i_pos = __ldg(&I[b]);
    const float ind   = (float)__ldg(&I_in[b]);
    const float n_u   = (float)__ldg(&N_U[b]);

    float a0 = 0.f, a1 = 0.f, a2 = 0.f, a3 = 0.f;
    #pragma unroll
    for (int k = 0; k < FK; k++) {
        const float* row = P + (size_t)s_idx[wid][k] * FD;
        if (VEC) {
            const float4 v = ldg_el4(reinterpret_cast<const float4*>(row) + lane);
            a0 += v.x; a1 += v.y; a2 += v.z; a3 += v.w;
        } else {
            a0 += __ldg(&row[lane]);
            a1 += __ldg(&row[lane + 32]);
            a2 += __ldg(&row[lane + 64]);
            a3 += __ldg(&row[lane + 96]);
        }
    }
    {   // exclude self if present
        const float* row = P + (size_t)i_pos * FD;
        if (VEC) {
            const float4 v = ldg_el4(reinterpret_cast<const float4*>(row) + lane);
            a0 -= v.x * ind; a1 -= v.y * ind; a2 -= v.z * ind; a3 -= v.w * ind;
        } else {
            a0 -= __ldg(&row[lane])      * ind;
            a1 -= __ldg(&row[lane + 32]) * ind;
            a2 -= __ldg(&row[lane + 64]) * ind;
            a3 -= __ldg(&row[lane + 96]) * ind;
        }
    }

    const float inv = 1.0f / fmaxf(n_u - ind, 1.0f);   // ALPHA = 1
    float* dst = g_pctx + (size_t)b * FD;
    if (VEC) {
        float4 o; o.x = a0 * inv; o.y = a1 * inv; o.z = a2 * inv; o.w = a3 * inv;
        reinterpret_cast<float4*>(dst)[lane] = o;       // dims [4l..4l+3]
    } else {
        dst[lane]      = a0 * inv;
        dst[lane + 32] = a1 * inv;
        dst[lane + 64] = a2 * inv;
        dst[lane + 96] = a3 * inv;
    }
}

// ---------------- kernel 2: 21 dots + biases -----------------------------
template<bool VEC>
__global__ __launch_bounds__(256, 6) void fism_dots(
    const int*   __restrict__ I,
    const int*   __restrict__ U,
    const int*   __restrict__ I_neg,
    const float* __restrict__ Q,
    const float* __restrict__ b_u,
    const float* __restrict__ b_i,
    float*       __restrict__ out)
{
    const int wid  = threadIdx.x >> 5;
    const int lane = threadIdx.x & 31;
    const int b    = blockIdx.x * WPB + wid;

    const int   i_pos = __ldg(&I[b]);
    const float bu    = __ldg(&b_u[__ldg(&U[b])]);
    const int   negi  = (lane < FNNEG) ? __ldg(&I_neg[(size_t)b * FNNEG + lane]) : 0;

    // load p_ctx_avg (layout matches kernel1's VEC flag)
    float p0, p1, p2, p3;
    const float* src = g_pctx + (size_t)b * FD;
    if (VEC) {
        const float4 v = reinterpret_cast<const float4*>(src)[lane];
        p0 = v.x; p1 = v.y; p2 = v.z; p3 = v.w;
    } else {
        p0 = src[lane]; p1 = src[lane + 32]; p2 = src[lane + 64]; p3 = src[lane + 96];
    }

    #pragma unroll
    for (int t = 0; t < 1 + FNNEG; t++) {
        const int item = (t == 0) ? i_pos : __shfl_sync(0xffffffffu, negi, t - 1);
        const float* qr = Q + (size_t)item * FD;
        float d;
        if (VEC) {
            const float4 v = ldg_el4(reinterpret_cast<const float4*>(qr) + lane);
            d = p0 * v.x + p1 * v.y + p2 * v.z + p3 * v.w;
        } else {
            d = p0 * __ldg(&qr[lane])
              + p1 * __ldg(&qr[lane + 32])
              + p2 * __ldg(&qr[lane + 64])
              + p3 * __ldg(&qr[lane + 96]);
        }
        #pragma unroll
        for (int off = 16; off > 0; off >>= 1)
            d += __shfl_down_sync(0xffffffffu, d, off);
        if (lane == 0) {
            const float val = bu + __ldg(&b_i[item]) + d;
            if (t == 0) out[b] = val;                                 // r
            else        out[FB + (size_t)b * FNNEG + (t - 1)] = val;  // r_neg
        }
    }
}

extern "C" void kernel_launch(void* const* d_in, const int* in_sizes, int n_in,
                              void* d_out, int out_size)
{
    const int*   I     = (const int*)  d_in[0];
    const int*   U     = (const int*)  d_in[1];
    const int*   I_neg = (const int*)  d_in[2];
    const int*   I_U   = (const int*)  d_in[3];
    const int*   N_U   = (const int*)  d_in[4];
    const int*   I_in  = (const int*)  d_in[5];
    const float* P     = (const float*)d_in[6];
    const float* Q     = (const float*)d_in[7];
    const float* b_u   = (const float*)d_in[8];
    const float* b_i   = (const float*)d_in[9];
    float* out = (float*)d_out;

    const bool aligned = (((uintptr_t)P & 15u) == 0) && (((uintptr_t)Q & 15u) == 0);
    dim3 grid(FB / WPB), block(32 * WPB);

    if (aligned) {
        fism_gather<true ><<<grid, block>>>(I, I_U, N_U, I_in, P);
        fism_dots  <true ><<<grid, block>>>(I, U, I_neg, Q, b_u, b_i, out);
    } else {
        fism_gather<false><<<grid, block>>>(I, I_U, N_U, I_in, P);
        fism_dots  <false><<<grid, block>>>(I, U, I_neg, Q, b_u, b_i, out);
    }
}

// round 6
// speedup vs baseline: 1.2461x; 1.2461x over previous
#include <cuda_runtime.h>
#include <cstddef>
#include <cstdint>

// FISM scoring: B=16384 rows, K=50 neighbors (contiguous slice of I_U),
// NNEG=20, D=128. Fused warp-per-row kernel:
//  - float4 gathers with L2 evict_last policy (tables stay L2-resident)
//  - __launch_bounds__(256,5) caps regs -> 40 warps/SM (vs 29 at 64 regs)
//  - xor-butterfly dot reduction; lane t keeps item t -> one coalesced
//    r_neg store per row instead of 20 divergent lane-0 stores.

#define FB    16384
#define FK    50
#define FNNEG 20
#define FD    128
#define WPB   8                      // warps (rows) per 256-thread block

// float4 gather with L2 evict_last cache hint
__device__ __forceinline__ float4 ldg_el4(const float4* p) {
    float4 v;
    asm("{\n\t"
        ".reg .b64 pol;\n\t"
        "createpolicy.fractional.L2::evict_last.b64 pol, 1.0;\n\t"
        "ld.global.nc.L2::cache_hint.v4.f32 {%0,%1,%2,%3}, [%4], pol;\n\t"
        "}"
        : "=f"(v.x), "=f"(v.y), "=f"(v.z), "=f"(v.w) : "l"(p));
    return v;
}

template<bool VEC>
__global__ __launch_bounds__(256, 5) void fism_fused(
    const int*   __restrict__ I,
    const int*   __restrict__ U,
    const int*   __restrict__ I_neg,
    const int*   __restrict__ I_U,
    const int*   __restrict__ N_U,
    const int*   __restrict__ I_in,
    const float* __restrict__ P,
    const float* __restrict__ Q,
    const float* __restrict__ b_u,
    const float* __restrict__ b_i,
    float*       __restrict__ out)
{
    const int wid  = threadIdx.x >> 5;
    const int lane = threadIdx.x & 31;
    const int b    = blockIdx.x * WPB + wid;     // FB = 2048*8 exact

    __shared__ int s_idx[WPB][FK];
    {
        const int* src = I_U + (size_t)b * FK;
        s_idx[wid][lane] = src[lane];
        if (lane < FK - 32) s_idx[wid][32 + lane] = src[32 + lane];
    }
    __syncwarp();

    // hoist ALL phase-2 scalars so their latency hides under the gather
    const int   i_pos = __ldg(&I[b]);
    const float ind   = (float)__ldg(&I_in[b]);
    const float n_u   = (float)__ldg(&N_U[b]);
    const float bu    = __ldg(&b_u[__ldg(&U[b])]);
    const int   negi  = (lane < FNNEG) ? __ldg(&I_neg[(size_t)b * FNNEG + lane]) : 0;
    const float bi_n  = (lane < FNNEG) ? __ldg(&b_i[negi]) : 0.0f;
    const float bi_p  = __ldg(&b_i[i_pos]);

    // ---- neighbor gather + sum ------------------------------------------
    float a0 = 0.f, a1 = 0.f, a2 = 0.f, a3 = 0.f;
    #pragma unroll
    for (int k = 0; k < FK; k++) {
        const float* row = P + (size_t)s_idx[wid][k] * FD;
        if (VEC) {
            const float4 v = ldg_el4(reinterpret_cast<const float4*>(row) + lane);
            a0 += v.x; a1 += v.y; a2 += v.z; a3 += v.w;
        } else {
            a0 += __ldg(&row[lane]);
            a1 += __ldg(&row[lane + 32]);
            a2 += __ldg(&row[lane + 64]);
            a3 += __ldg(&row[lane + 96]);
        }
    }
    {   // exclude self if present
        const float* row = P + (size_t)i_pos * FD;
        if (VEC) {
            const float4 v = ldg_el4(reinterpret_cast<const float4*>(row) + lane);
            a0 -= v.x * ind; a1 -= v.y * ind; a2 -= v.z * ind; a3 -= v.w * ind;
        } else {
            a0 -= __ldg(&row[lane])      * ind;
            a1 -= __ldg(&row[lane + 32]) * ind;
            a2 -= __ldg(&row[lane + 64]) * ind;
            a3 -= __ldg(&row[lane + 96]) * ind;
        }
    }

    const float inv = 1.0f / fmaxf(n_u - ind, 1.0f);   // ALPHA = 1
    const float p0 = a0 * inv, p1 = a1 * inv, p2 = a2 * inv, p3 = a3 * inv;

    // ---- 21 dot products; lane t keeps item t's score -------------------
    float my_neg = 0.0f;   // lane t (t<20): r_neg[b][t]
    float r_pos  = 0.0f;

    #pragma unroll
    for (int t = 0; t < 1 + FNNEG; t++) {
        const int item = (t == 0) ? i_pos : __shfl_sync(0xffffffffu, negi, t - 1);
        const float* qr = Q + (size_t)item * FD;
        float d;
        if (VEC) {
            const float4 v = ldg_el4(reinterpret_cast<const float4*>(qr) + lane);
            d = p0 * v.x + p1 * v.y + p2 * v.z + p3 * v.w;
        } else {
            d = p0 * __ldg(&qr[lane])
              + p1 * __ldg(&qr[lane + 32])
              + p2 * __ldg(&qr[lane + 64])
              + p3 * __ldg(&qr[lane + 96]);
        }
        #pragma unroll
        for (int off = 16; off > 0; off >>= 1)
            d += __shfl_xor_sync(0xffffffffu, d, off);   // result in all lanes
        if (t == 0)               r_pos  = d;
        else if (lane == t - 1)   my_neg = d;
    }

    // coalesced epilogue: one 20-wide store + one scalar
    if (lane < FNNEG)
        out[FB + (size_t)b * FNNEG + lane] = bu + bi_n + my_neg;
    if (lane == 0)
        out[b] = bu + bi_p + r_pos;
}

extern "C" void kernel_launch(void* const* d_in, const int* in_sizes, int n_in,
                              void* d_out, int out_size)
{
    const int*   I     = (const int*)  d_in[0];
    const int*   U     = (const int*)  d_in[1];
    const int*   I_neg = (const int*)  d_in[2];
    const int*   I_U   = (const int*)  d_in[3];
    const int*   N_U   = (const int*)  d_in[4];
    const int*   I_in  = (const int*)  d_in[5];
    const float* P     = (const float*)d_in[6];
    const float* Q     = (const float*)d_in[7];
    const float* b_u   = (const float*)d_in[8];
    const float* b_i   = (const float*)d_in[9];
    float* out = (float*)d_out;

    const bool aligned = (((uintptr_t)P & 15u) == 0) && (((uintptr_t)Q & 15u) == 0);
    dim3 grid(FB / WPB), block(32 * WPB);

    if (aligned)
        fism_fused<true ><<<grid, block>>>(I, U, I_neg, I_U, N_U, I_in, P, Q, b_u, b_i, out);
    else
        fism_fused<false><<<grid, block>>>(I, U, I_neg, I_U, N_U, I_in, P, Q, b_u, b_i, out);
}